// round 13
// baseline (speedup 1.0000x reference)
#include <cuda_runtime.h>

// ---------------------------------------------------------------------------
// 5-layer stacked LSTM, H=51, B=256, T=2048. Output depends only on layer-3 h
// => layers 4,5 dead. 3 roles (L1,L2,L3) x 32 batch groups = 96 CTAs.
// DECOUPLED BARRIER DOMAINS (R12 structure, scaled to 27 warps):
//   R group (warps 0-12):  recurrent GEMV(t) -> cell(t)   [serial chain]
//   I group (warps 13-25): input GEMV(s), one step ahead
//   comm warp (26):        ring prefetch D=4, paced with I
// Both GEMVs: 408 lanes, 2 rows x quarter-k (13 iters) per lane.
// tanh.approx activations (sigmoid x/2 folded into weights), c in registers.
// ---------------------------------------------------------------------------

#define HN 51
#define NJ 204
#define TN 2048
#define NG 32
#define BT 8
#define NSLOT 16
#define XBUF 8
#define DPRE 4
#define NTH 864
#define I0   416              // first tid of I group
#define C0   832              // first tid of comm warp
#define RACT 408              // active GEMV lanes per group
#define EBT  408              // HN*BT
#define GSZ  1632             // NJ*BT
#define KIT  13

// named barrier ids / counts
#define B_IN0 2
#define B_FR0 4
#define B_RH  6
#define B_XC  7
#define CNT_RI 832            // R(416) + I(416)
#define CNT_R  416
#define CNT_XC 448            // I(416) + comm(32)

typedef unsigned long long ull;

__device__ float    g_hbuf[2][NG][NSLOT][EBT];
__device__ unsigned g_prod[2][NG];
__device__ unsigned g_cons[2][NG];

__device__ __forceinline__ unsigned ld_acq(const unsigned* p) {
    unsigned v;
    asm volatile("ld.global.acquire.gpu.u32 %0, [%1];" : "=r"(v) : "l"(p));
    return v;
}
__device__ __forceinline__ void st_rel(unsigned* p, unsigned v) {
    asm volatile("st.global.release.gpu.u32 [%0], %1;" :: "l"(p), "r"(v));
}
__device__ __forceinline__ void wait_ge(unsigned* p, unsigned v) {
    if (ld_acq(p) >= v) return;
    while (ld_acq(p) < v) __nanosleep(32);
}
__device__ __forceinline__ float4 ldcg4(const float4* p) {
    float4 v;
    asm volatile("ld.global.cg.v4.f32 {%0,%1,%2,%3}, [%4];"
                 : "=f"(v.x), "=f"(v.y), "=f"(v.z), "=f"(v.w) : "l"(p));
    return v;
}
__device__ __forceinline__ ull ffma2(ull a, ull b, ull c) {
    ull d;
    asm("fma.rn.f32x2 %0, %1, %2, %3;" : "=l"(d) : "l"(a), "l"(b), "l"(c));
    return d;
}
__device__ __forceinline__ ull splat2(float x) {
    ull d; unsigned u = __float_as_uint(x);
    asm("mov.b64 %0, {%1, %2};" : "=l"(d) : "r"(u), "r"(u));
    return d;
}
__device__ __forceinline__ float tanha(float x) {
    float y;
    asm("tanh.approx.f32 %0, %1;" : "=f"(y) : "f"(x));
    return y;
}
__device__ __forceinline__ float sig_h(float y) {   // arg pre-halved
    return fmaf(0.5f, tanha(y), 0.5f);
}
#define BAR_SYNC(id, cnt)   asm volatile("bar.sync %0, %1;"   :: "r"(id), "r"(cnt) : "memory")
#define BAR_ARRIVE(id, cnt) asm volatile("bar.arrive %0, %1;" :: "r"(id), "r"(cnt) : "memory")
#define MEMBAR_CTA()        asm volatile("membar.cta;" ::: "memory")

__global__ void __launch_bounds__(64, 1) reset_kernel() {
    int i = threadIdx.x;
    if (i < NG) {
        g_prod[0][i] = 0; g_prod[1][i] = 0;
        g_cons[0][i] = 0; g_cons[1][i] = 0;
    }
}

__global__ void __launch_bounds__(NTH, 1) lstm_kernel(
    const float* __restrict__ x,    const float* __restrict__ Wih1,
    const float* __restrict__ Whh1, const float* __restrict__ bih1,
    const float* __restrict__ bhh1, const float* __restrict__ Wih,
    const float* __restrict__ Whh,  const float* __restrict__ bih,
    const float* __restrict__ bhh,  const float* __restrict__ Wl,
    const float* __restrict__ bl,   float* __restrict__ out)
{
    extern __shared__ float sm[];
    float* grec = sm;                 // [4 kq][GSZ]           6528
    float* gin  = sm + 6528;          // [2 par][4 kq][GSZ]    13056
    float* xin  = sm + 19584;         // [XBUF][52*8]          3328 (row 51 zero)
    float* h_t  = sm + 22912;         // [52*8] (row 51 zero)  416
    float* xchk = sm + 23328;         // [2][32][8]            512
    float* wl_s = sm + 23840;         // [52]
    // total 23892 floats = 95568 bytes

    const int tid  = threadIdx.x;
    const int role = blockIdx.x / NG;   // 0=L1, 1=L2, 2=L3
    const int g    = blockIdx.x % NG;

    // ---------------- group-specific weight loads ----------------
    float wr0[KIT], wr1[KIT];          // R lanes: 2 rows x quarter-k
    float wi0[KIT], wi1[KIT];          // I lanes: 2 rows x quarter-k
    ull biasA = 0, biasB = 0, w1A = 0, w1B = 0;
    int kb = 0, r0 = 0;

    if (tid < RACT) {                       // R GEMV lane
        const int kq = tid / 102, jp = tid % 102;
        r0 = 2 * jp; kb = kq * KIT;
        const float* W = (role == 0) ? Whh1 : (Whh + (role - 1) * NJ * HN);
        const float sc0 = ((r0     / 51) == 2) ? 1.f : 0.5f;
        const float sc1 = (((r0+1) / 51) == 2) ? 1.f : 0.5f;
        #pragma unroll
        for (int kk = 0; kk < KIT; kk++) {
            int k = kb + kk;
            bool ok = (k < HN);
            wr0[kk] = ok ? sc0 * W[ r0      * HN + k] : 0.f;
            wr1[kk] = ok ? sc1 * W[(r0 + 1) * HN + k] : 0.f;
        }
    } else if (tid >= I0 && tid < I0 + RACT) {   // I GEMV lane
        const int itid = tid - I0;
        const int kq = itid / 102, jp = itid % 102;
        r0 = 2 * jp; kb = kq * KIT;
        const float sc0 = ((r0     / 51) == 2) ? 1.f : 0.5f;
        const float sc1 = (((r0+1) / 51) == 2) ? 1.f : 0.5f;
        if (role > 0) {
            const int l = role - 1;
            const float* W = Wih + l * NJ * HN;
            #pragma unroll
            for (int kk = 0; kk < KIT; kk++) {
                int k = kb + kk;
                bool ok = (k < HN);
                wi0[kk] = ok ? sc0 * W[ r0      * HN + k] : 0.f;
                wi1[kk] = ok ? sc1 * W[(r0 + 1) * HN + k] : 0.f;
            }
            if (kq == 0) {
                biasA = splat2(sc0 * (bih[l * NJ + r0]     + bhh[l * NJ + r0]));
                biasB = splat2(sc1 * (bih[l * NJ + r0 + 1] + bhh[l * NJ + r0 + 1]));
            }
        } else if (kq == 0) {   // role 0: rank-1 input term
            w1A   = splat2(sc0 * Wih1[r0]);
            w1B   = splat2(sc1 * Wih1[r0 + 1]);
            biasA = splat2(sc0 * (bih1[r0]     + bhh1[r0]));
            biasB = splat2(sc1 * (bih1[r0 + 1] + bhh1[r0 + 1]));
        }
    }
    if (role == 2 && tid < HN) wl_s[tid] = Wl[tid];
    const float blv = (role == 2) ? bl[0] : 0.f;

    for (int i = tid; i < 23892; i += NTH) sm[i] = 0.f;
    __syncthreads();
    if (role == 2 && tid < HN) wl_s[tid] = Wl[tid];   // rewrite after zero
    __syncthreads();

    float*       ring_out = (role < 2) ? &g_hbuf[role][g][0][0]     : (float*)0;
    const float* ring_in  = (role > 0) ? &g_hbuf[role - 1][g][0][0] : (const float*)0;

    // ---- prologue: comm warp fills xin slots 0..DPRE-1 / x window 0 ----
    if (tid >= C0) {
        const int lane = tid - C0;
        if (role > 0) {
            for (int d = 0; d < DPRE; d++) {
                if (lane == 0) wait_ge(&g_prod[role - 1][g], (unsigned)(d + 1));
                __syncwarp();
                const float4* s4 = (const float4*)(ring_in + d * EBT);
                float4* d4 = (float4*)(xin + d * 416);
                for (int i = lane; i < EBT / 4; i += 32) d4[i] = ldcg4(s4 + i);
                __syncwarp();
                if (lane == 0) st_rel(&g_cons[role - 1][g], (unsigned)(d + 1));
            }
        } else {
            #pragma unroll
            for (int b = 0; b < BT; b++)
                xchk[lane * 8 + b] = x[(size_t)(g * BT + b) * TN + lane];
        }
    }
    __syncthreads();

    // =====================================================================
    if (tid < I0) {
        // ============================ R group ============================
        float c_reg = 0.f;
        const int  kq = (tid < RACT) ? tid / 102 : 0;
        const bool lane_out = (role == 2) && (tid >= RACT && tid < RACT + BT);
        const bool lane_bp  = (role <  2) && (tid == RACT);

        for (int t = 0; t < TN; t++) {
            // ---- recurrent GEMV(t) over h(t-1) ----
            if (tid < RACT) {
                const ulonglong2* hp = (const ulonglong2*)(h_t + kb * BT);
                ull a00 = 0, a01 = 0, a02 = 0, a03 = 0;
                ull a10 = 0, a11 = 0, a12 = 0, a13 = 0;
                #pragma unroll
                for (int kk = 0; kk < KIT; kk++) {
                    ulonglong2 S0 = hp[2 * kk], S1 = hp[2 * kk + 1];
                    ull w0 = splat2(wr0[kk]);
                    ull w1 = splat2(wr1[kk]);
                    a00 = ffma2(S0.x, w0, a00); a01 = ffma2(S0.y, w0, a01);
                    a02 = ffma2(S1.x, w0, a02); a03 = ffma2(S1.y, w0, a03);
                    a10 = ffma2(S0.x, w1, a10); a11 = ffma2(S0.y, w1, a11);
                    a12 = ffma2(S1.x, w1, a12); a13 = ffma2(S1.y, w1, a13);
                }
                float* gr = grec + kq * GSZ + r0 * BT;
                ulonglong2 s;
                s.x = a00; s.y = a01; *(ulonglong2*)(gr)          = s;
                s.x = a02; s.y = a03; *(ulonglong2*)(gr + 4)      = s;
                s.x = a10; s.y = a11; *(ulonglong2*)(gr + BT)     = s;
                s.x = a12; s.y = a13; *(ulonglong2*)(gr + BT + 4) = s;
            } else {
                if (lane_out && t > 0) {                 // out(t-1) from h(t-1)
                    const int b = tid - RACT;
                    float a = blv;
                    #pragma unroll
                    for (int u = 0; u < HN; u++) a += h_t[u * BT + b] * wl_s[u];
                    out[(size_t)(g * BT + b) * TN + (t - 1)] = a;
                }
                if (lane_bp && t >= NSLOT)
                    wait_ge(&g_cons[role][g], (unsigned)(t - (NSLOT - 1)));
            }

            BAR_SYNC(B_IN0 + (t & 1), CNT_RI);   // input gates(t) ready

            // ---- cell(t): 1 element/thread ----
            if (tid < RACT) {
                const int e = tid;
                const float* gi = gin + (t & 1) * 4 * GSZ;
                float yi = 0.f, yf = 0.f, gg = 0.f, yo = 0.f;
                #pragma unroll
                for (int q = 0; q < 4; q++) {
                    const float* gq = grec + q * GSZ;
                    yi += gq[e];        yf += gq[408 + e];
                    gg += gq[816 + e];  yo += gq[1224 + e];
                }
                #pragma unroll
                for (int q = 0; q < 4; q++) {
                    const float* gq = gi + q * GSZ;
                    yi += gq[e];        yf += gq[408 + e];
                    gg += gq[816 + e];  yo += gq[1224 + e];
                }
                float c = sig_h(yf) * c_reg + sig_h(yi) * tanha(gg);
                float h = sig_h(yo) * tanha(c);
                c_reg = c;
                h_t[e] = h;
                if (role < 2) ring_out[(t & (NSLOT - 1)) * EBT + e] = h;
            }

            BAR_ARRIVE(B_FR0 + (t & 1), CNT_RI); // gin(t) consumed
            BAR_SYNC(B_RH, CNT_R);               // h(t) + ring STGs complete
            if (role < 2 && tid == 0) st_rel(&g_prod[role][g], (unsigned)(t + 1));
        }
        // epilogue: out(TN-1)
        if (lane_out) {
            const int b = tid - RACT;
            float a = blv;
            #pragma unroll
            for (int u = 0; u < HN; u++) a += h_t[u * BT + b] * wl_s[u];
            out[(size_t)(g * BT + b) * TN + (TN - 1)] = a;
        }
    } else if (tid < C0) {
        // ============================ I group ============================
        const int itid = tid - I0;
        const int kq   = (itid < RACT) ? itid / 102 : 0;

        for (int s = 0; s < TN; s++) {
            BAR_SYNC(B_XC, CNT_XC);                        // xin(s)/xchk ready
            if (s >= 2) BAR_SYNC(B_FR0 + (s & 1), CNT_RI); // gin[s&1] free

            if (itid < RACT) {
                float* gq = gin + (s & 1) * 4 * GSZ + kq * GSZ;
                if (role > 0) {
                    const ulonglong2* sp =
                        (const ulonglong2*)(xin + (s & (XBUF - 1)) * 416 + kb * BT);
                    ull a00 = biasA, a01 = biasA, a02 = biasA, a03 = biasA;
                    ull a10 = biasB, a11 = biasB, a12 = biasB, a13 = biasB;
                    #pragma unroll
                    for (int kk = 0; kk < KIT; kk++) {
                        ulonglong2 S0 = sp[2 * kk], S1 = sp[2 * kk + 1];
                        ull w0 = splat2(wi0[kk]);
                        ull w1 = splat2(wi1[kk]);
                        a00 = ffma2(S0.x, w0, a00); a01 = ffma2(S0.y, w0, a01);
                        a02 = ffma2(S1.x, w0, a02); a03 = ffma2(S1.y, w0, a03);
                        a10 = ffma2(S0.x, w1, a10); a11 = ffma2(S0.y, w1, a11);
                        a12 = ffma2(S1.x, w1, a12); a13 = ffma2(S1.y, w1, a13);
                    }
                    ulonglong2 v;
                    float* gw = gq + r0 * BT;
                    v.x = a00; v.y = a01; *(ulonglong2*)(gw)          = v;
                    v.x = a02; v.y = a03; *(ulonglong2*)(gw + 4)      = v;
                    v.x = a10; v.y = a11; *(ulonglong2*)(gw + BT)     = v;
                    v.x = a12; v.y = a13; *(ulonglong2*)(gw + BT + 4) = v;
                } else if (kq == 0) {   // role 0 rank-1 input term
                    const ulonglong2* xp =
                        (const ulonglong2*)(xchk + ((s >> 5) & 1) * 256 + (s & 31) * 8);
                    ulonglong2 X0 = xp[0], X1 = xp[1];
                    ull a0 = ffma2(X0.x, w1A, biasA);
                    ull a1 = ffma2(X0.y, w1A, biasA);
                    ull a2 = ffma2(X1.x, w1A, biasA);
                    ull a3 = ffma2(X1.y, w1A, biasA);
                    ull b0 = ffma2(X0.x, w1B, biasB);
                    ull b1 = ffma2(X0.y, w1B, biasB);
                    ull b2 = ffma2(X1.x, w1B, biasB);
                    ull b3 = ffma2(X1.y, w1B, biasB);
                    ulonglong2 v;
                    float* gw = gq + r0 * BT;
                    v.x = a0; v.y = a1; *(ulonglong2*)(gw)          = v;
                    v.x = a2; v.y = a3; *(ulonglong2*)(gw + 4)      = v;
                    v.x = b0; v.y = b1; *(ulonglong2*)(gw + BT)     = v;
                    v.x = b2; v.y = b3; *(ulonglong2*)(gw + BT + 4) = v;
                }
            }
            MEMBAR_CTA();
            BAR_ARRIVE(B_IN0 + (s & 1), CNT_RI);   // gin(s) ready
        }
    } else {
        // ============================ comm warp ============================
        const int lane = tid - C0;
        for (int k = 0; k < TN; k++) {
            BAR_SYNC(B_XC, CNT_XC);
            if (role > 0 && k + DPRE < TN) {
                if (lane == 0) wait_ge(&g_prod[role - 1][g], (unsigned)(k + DPRE + 1));
                __syncwarp();
                const float4* s4 =
                    (const float4*)(ring_in + ((k + DPRE) & (NSLOT - 1)) * EBT);
                float4* d4 = (float4*)(xin + ((k + DPRE) & (XBUF - 1)) * 416);
                for (int i = lane; i < EBT / 4; i += 32) d4[i] = ldcg4(s4 + i);
                __syncwarp();
                if (lane == 0) st_rel(&g_cons[role - 1][g], (unsigned)(k + DPRE + 1));
            }
            if (role == 0 && (k & 31) == 0 && k + 32 < TN) {
                const int w = ((k >> 5) + 1) & 1;
                #pragma unroll
                for (int b = 0; b < BT; b++)
                    xchk[w * 256 + lane * 8 + b] =
                        x[(size_t)(g * BT + b) * TN + (k + 32 + lane)];
            }
        }
    }
}

extern "C" void kernel_launch(void* const* d_in, const int* in_sizes, int n_in,
                              void* d_out, int out_size)
{
    (void)in_sizes; (void)n_in; (void)out_size;
    const float* x    = (const float*)d_in[0];
    const float* Wih1 = (const float*)d_in[1];
    const float* Whh1 = (const float*)d_in[2];
    const float* bih1 = (const float*)d_in[3];
    const float* bhh1 = (const float*)d_in[4];
    const float* Wih  = (const float*)d_in[5];
    const float* Whh  = (const float*)d_in[6];
    const float* bih  = (const float*)d_in[7];
    const float* bhh  = (const float*)d_in[8];
    const float* Wl   = (const float*)d_in[9];
    const float* bl   = (const float*)d_in[10];
    float* out = (float*)d_out;

    const int smem_bytes = 23892 * 4;  // 95568
    cudaFuncSetAttribute(lstm_kernel, cudaFuncAttributeMaxDynamicSharedMemorySize,
                         smem_bytes);

    reset_kernel<<<1, 64>>>();
    lstm_kernel<<<3 * NG, NTH, smem_bytes>>>(x, Wih1, Whh1, bih1, bhh1,
                                             Wih, Whh, bih, bhh, Wl, bl, out);
}

// round 14
// speedup vs baseline: 1.1855x; 1.1855x over previous
#include <cuda_runtime.h>

// ---------------------------------------------------------------------------
// 5-layer stacked LSTM, H=51, B=256, T=2048. Output depends only on layer-3 h
// => layers 4,5 dead. 3 roles (L1,L2,L3) x 32 batch groups = 96 CTAs.
// R12 decoupled-domain structure (the measured optimum: 15 warps):
//   R group (warps 0-6):  recurrent GEMV(t) -> cell(t)   [serial chain]
//   I group (warps 7-13): input GEMV(s) + QUADRANT PRE-SUM, up to 4 ahead
//   comm warp (14):       ring prefetch D=4, paced with I
// New vs R12: I pre-reduces its 4 gin quadrants into ginsum (cell loads halve),
// and I->R handoff is 4-deep (parity t&3) to absorb jitter.
// ---------------------------------------------------------------------------

#define HN 51
#define NJ 204
#define TN 2048
#define NG 32
#define BT 8
#define NSLOT 16
#define XBUF 8
#define DPRE 4
#define NTH 480
#define I0   224              // first tid of I group
#define C0   448              // first tid of comm warp
#define EBT  408              // HN*BT
#define GSZ  1632             // NJ*BT

// named barrier ids / counts
#define B_IN0 2               // ids 2..5  : gin(s) ready   (I arrive, R sync)
#define B_FR0 6               // ids 6..9  : ginsum slot free (R arrive, I sync)
#define B_RH  10              // R-internal: h(t) complete
#define B_XC  11              // I+comm pacing
#define B_II  12              // I-internal: quadrants written
#define CNT_RI 448
#define CNT_R  224
#define CNT_I  224
#define CNT_XC 256

typedef unsigned long long ull;

__device__ float    g_hbuf[2][NG][NSLOT][EBT];
__device__ unsigned g_prod[2][NG];
__device__ unsigned g_cons[2][NG];

__device__ __forceinline__ unsigned ld_acq(const unsigned* p) {
    unsigned v;
    asm volatile("ld.global.acquire.gpu.u32 %0, [%1];" : "=r"(v) : "l"(p));
    return v;
}
__device__ __forceinline__ void st_rel(unsigned* p, unsigned v) {
    asm volatile("st.global.release.gpu.u32 [%0], %1;" :: "l"(p), "r"(v));
}
__device__ __forceinline__ void wait_ge(unsigned* p, unsigned v) {
    if (ld_acq(p) >= v) return;
    while (ld_acq(p) < v) __nanosleep(32);
}
__device__ __forceinline__ float4 ldcg4(const float4* p) {
    float4 v;
    asm volatile("ld.global.cg.v4.f32 {%0,%1,%2,%3}, [%4];"
                 : "=f"(v.x), "=f"(v.y), "=f"(v.z), "=f"(v.w) : "l"(p));
    return v;
}
__device__ __forceinline__ ull ffma2(ull a, ull b, ull c) {
    ull d;
    asm("fma.rn.f32x2 %0, %1, %2, %3;" : "=l"(d) : "l"(a), "l"(b), "l"(c));
    return d;
}
__device__ __forceinline__ ull splat2(float x) {
    ull d; unsigned u = __float_as_uint(x);
    asm("mov.b64 %0, {%1, %2};" : "=l"(d) : "r"(u), "r"(u));
    return d;
}
__device__ __forceinline__ float tanha(float x) {
    float y;
    asm("tanh.approx.f32 %0, %1;" : "=f"(y) : "f"(x));
    return y;
}
__device__ __forceinline__ float sig_h(float y) {   // arg pre-halved
    return fmaf(0.5f, tanha(y), 0.5f);
}
#define BAR_SYNC(id, cnt)   asm volatile("bar.sync %0, %1;"   :: "r"(id), "r"(cnt) : "memory")
#define BAR_ARRIVE(id, cnt) asm volatile("bar.arrive %0, %1;" :: "r"(id), "r"(cnt) : "memory")
#define MEMBAR_CTA()        asm volatile("membar.cta;" ::: "memory")

__global__ void __launch_bounds__(64, 1) reset_kernel() {
    int i = threadIdx.x;
    if (i < NG) {
        g_prod[0][i] = 0; g_prod[1][i] = 0;
        g_cons[0][i] = 0; g_cons[1][i] = 0;
    }
}

__global__ void __launch_bounds__(NTH, 1) lstm_kernel(
    const float* __restrict__ x,    const float* __restrict__ Wih1,
    const float* __restrict__ Whh1, const float* __restrict__ bih1,
    const float* __restrict__ bhh1, const float* __restrict__ Wih,
    const float* __restrict__ Whh,  const float* __restrict__ bih,
    const float* __restrict__ bhh,  const float* __restrict__ Wl,
    const float* __restrict__ bl,   float* __restrict__ out)
{
    extern __shared__ float sm[];
    float* grec   = sm;               // [2 kh][GSZ]           3264
    float* ginq   = sm + 3264;        // [2 buf][4 kq][GSZ]    13056 (I scratch)
    float* ginsum = sm + 16320;       // [4 par][GSZ]          6528
    float* xin    = sm + 22848;       // [XBUF][52*8]          3328 (row 51 zero)
    float* h_t    = sm + 26176;       // [52*8] (row 51 zero)  416
    float* xchk   = sm + 26592;       // [2][32][8]            512
    float* wl_s   = sm + 27104;       // [52]
    // total 27156 floats = 108624 bytes

    const int tid  = threadIdx.x;
    const int role = blockIdx.x / NG;   // 0=L1, 1=L2, 2=L3
    const int g    = blockIdx.x % NG;

    // ---------------- group-specific weight loads (R12-identical) ----------
    float wr0[26], wr1[26];            // R lanes: 2 rows x half-k
    int r_kbase = 0, r_r0 = 0;
    float wi[4][13];                   // I lanes: 4 rows x quarter-k
    ull bias2[4], w1_2[4];
    #pragma unroll
    for (int G = 0; G < 4; G++) { bias2[G] = 0; w1_2[G] = 0; }

    if (tid < 204) {                      // R GEMV lane
        const int kh = tid / 102, jp = tid % 102;
        r_r0 = 2 * jp; r_kbase = kh * 25;
        const float* W = (role == 0) ? Whh1 : (Whh + (role - 1) * NJ * HN);
        const float sc0 = ((r_r0     / 51) == 2) ? 1.f : 0.5f;
        const float sc1 = (((r_r0+1) / 51) == 2) ? 1.f : 0.5f;
        #pragma unroll
        for (int kk = 0; kk < 26; kk++) {
            int k = r_kbase + kk;
            bool z = (kh == 1 && kk == 0);
            wr0[kk] = z ? 0.f : sc0 * W[ r_r0      * HN + k];
            wr1[kk] = z ? 0.f : sc1 * W[(r_r0 + 1) * HN + k];
        }
    } else if (tid >= I0 && tid < I0 + 204) {   // I GEMV lane
        const int itid = tid - I0;
        const int kq = itid / 51, j = itid % 51;
        const int kbase = kq * 13;
        if (role > 0) {
            const int l = role - 1;
            const float* W = Wih + l * NJ * HN;
            #pragma unroll
            for (int G = 0; G < 4; G++) {
                const float sc = (G == 2) ? 1.f : 0.5f;
                #pragma unroll
                for (int kk = 0; kk < 13; kk++) {
                    int k = kbase + kk;
                    wi[G][kk] = (k < HN) ? sc * W[(G * 51 + j) * HN + k] : 0.f;
                }
            }
            if (kq == 0)
                #pragma unroll
                for (int G = 0; G < 4; G++) {
                    const float sc = (G == 2) ? 1.f : 0.5f;
                    bias2[G] = splat2(sc * (bih[l * NJ + G * 51 + j]
                                          + bhh[l * NJ + G * 51 + j]));
                }
        } else if (kq == 0) {   // role 0 rank-1 input
            #pragma unroll
            for (int G = 0; G < 4; G++) {
                const float sc = (G == 2) ? 1.f : 0.5f;
                w1_2[G]  = splat2(sc * Wih1[G * 51 + j]);
                bias2[G] = splat2(sc * (bih1[G * 51 + j] + bhh1[G * 51 + j]));
            }
        }
    }
    const float blv = (role == 2) ? bl[0] : 0.f;

    for (int i = tid; i < 27156; i += NTH) sm[i] = 0.f;
    __syncthreads();
    if (role == 2 && tid < HN) wl_s[tid] = Wl[tid];
    __syncthreads();

    float*       ring_out = (role < 2) ? &g_hbuf[role][g][0][0]     : (float*)0;
    const float* ring_in  = (role > 0) ? &g_hbuf[role - 1][g][0][0] : (const float*)0;

    // ---- prologue: comm warp fills xin slots 0..3 / x window 0 ----
    if (tid >= C0) {
        const int lane = tid - C0;
        if (role > 0) {
            for (int d = 0; d < DPRE; d++) {
                if (lane == 0) wait_ge(&g_prod[role - 1][g], (unsigned)(d + 1));
                __syncwarp();
                const float4* s4 = (const float4*)(ring_in + d * EBT);
                float4* d4 = (float4*)(xin + d * 416);
                for (int i = lane; i < EBT / 4; i += 32) d4[i] = ldcg4(s4 + i);
                __syncwarp();
                if (lane == 0) st_rel(&g_cons[role - 1][g], (unsigned)(d + 1));
            }
        } else {
            #pragma unroll
            for (int b = 0; b < BT; b++)
                xchk[lane * 8 + b] = x[(size_t)(g * BT + b) * TN + lane];
        }
    }
    __syncthreads();

    // =====================================================================
    if (tid < I0) {
        // ============================ R group ============================
        float c_a = 0.f, c_b = 0.f;
        const bool lane_out = (role == 2) && (tid >= 204 && tid < 212);
        const bool lane_bp  = (role <  2) && (tid == 212);

        for (int t = 0; t < TN; t++) {
            // ---- recurrent GEMV(t) over h(t-1) ----
            if (tid < 204) {
                const ulonglong2* hp = (const ulonglong2*)(h_t + r_kbase * BT);
                ull a00 = 0, a01 = 0, a02 = 0, a03 = 0;
                ull a10 = 0, a11 = 0, a12 = 0, a13 = 0;
                #pragma unroll
                for (int kk = 0; kk < 26; kk++) {
                    ulonglong2 S0 = hp[2 * kk], S1 = hp[2 * kk + 1];
                    ull w0 = splat2(wr0[kk]);
                    ull w1 = splat2(wr1[kk]);
                    a00 = ffma2(S0.x, w0, a00); a01 = ffma2(S0.y, w0, a01);
                    a02 = ffma2(S1.x, w0, a02); a03 = ffma2(S1.y, w0, a03);
                    a10 = ffma2(S0.x, w1, a10); a11 = ffma2(S0.y, w1, a11);
                    a12 = ffma2(S1.x, w1, a12); a13 = ffma2(S1.y, w1, a13);
                }
                float* gr = grec + (tid / 102) * GSZ + r_r0 * BT;
                ulonglong2 s;
                s.x = a00; s.y = a01; *(ulonglong2*)(gr)          = s;
                s.x = a02; s.y = a03; *(ulonglong2*)(gr + 4)      = s;
                s.x = a10; s.y = a11; *(ulonglong2*)(gr + BT)     = s;
                s.x = a12; s.y = a13; *(ulonglong2*)(gr + BT + 4) = s;
            } else {
                if (lane_out && t > 0) {                 // out(t-1) from h(t-1)
                    const int b = tid - 204;
                    float a = blv;
                    #pragma unroll
                    for (int u = 0; u < HN; u++) a += h_t[u * BT + b] * wl_s[u];
                    out[(size_t)(g * BT + b) * TN + (t - 1)] = a;
                }
                if (lane_bp && t >= NSLOT)
                    wait_ge(&g_cons[role][g], (unsigned)(t - (NSLOT - 1)));
            }

            BAR_SYNC(B_IN0 + (t & 3), CNT_RI);   // ginsum(t) ready; grec drained

            // ---- cell(t): elements tid and tid+224 (12 LDS/elem) ----
            {
                const float* gs = ginsum + (t & 3) * GSZ;
                float* rslot = (role < 2) ? (ring_out + (t & (NSLOT - 1)) * EBT)
                                          : (float*)0;
                {
                    const int e = tid;
                    float yi = grec[e]        + grec[GSZ + e]        + gs[e];
                    float yf = grec[408 + e]  + grec[GSZ + 408 + e]  + gs[408 + e];
                    float gg = grec[816 + e]  + grec[GSZ + 816 + e]  + gs[816 + e];
                    float yo = grec[1224 + e] + grec[GSZ + 1224 + e] + gs[1224 + e];
                    float c = sig_h(yf) * c_a + sig_h(yi) * tanha(gg);
                    float h = sig_h(yo) * tanha(c);
                    c_a = c; h_t[e] = h;
                    if (role < 2) rslot[e] = h;
                }
                if (tid < 184) {
                    const int e = tid + 224;
                    float yi = grec[e]        + grec[GSZ + e]        + gs[e];
                    float yf = grec[408 + e]  + grec[GSZ + 408 + e]  + gs[408 + e];
                    float gg = grec[816 + e]  + grec[GSZ + 816 + e]  + gs[816 + e];
                    float yo = grec[1224 + e] + grec[GSZ + 1224 + e] + gs[1224 + e];
                    float c = sig_h(yf) * c_b + sig_h(yi) * tanha(gg);
                    float h = sig_h(yo) * tanha(c);
                    c_b = c; h_t[e] = h;
                    if (role < 2) rslot[e] = h;
                }
            }

            BAR_ARRIVE(B_FR0 + (t & 3), CNT_RI); // ginsum slot (t&3) consumed
            BAR_SYNC(B_RH, CNT_R);               // h(t) + ring STGs complete
            if (role < 2 && tid == 0) st_rel(&g_prod[role][g], (unsigned)(t + 1));
        }
        // epilogue: out(TN-1)
        if (lane_out) {
            const int b = tid - 204;
            float a = blv;
            #pragma unroll
            for (int u = 0; u < HN; u++) a += h_t[u * BT + b] * wl_s[u];
            out[(size_t)(g * BT + b) * TN + (TN - 1)] = a;
        }
    } else if (tid < C0) {
        // ============================ I group ============================
        const int itid = tid - I0;
        const int kq = (itid < 204) ? itid / 51 : 0;
        const int j  = (itid < 204) ? itid % 51 : 0;
        const int kbase = kq * 13;

        for (int s = 0; s < TN; s++) {
            BAR_SYNC(B_XC, CNT_XC);                        // xin(s)/xchk ready
            if (s >= 4) BAR_SYNC(B_FR0 + (s & 3), CNT_RI); // ginsum[s&3] free

            if (itid < 204) {
                float* gq = ginq + (s & 1) * 4 * GSZ + kq * GSZ;
                if (role > 0) {
                    const ulonglong2* sp =
                        (const ulonglong2*)(xin + (s & (XBUF - 1)) * 416 + kbase * BT);
                    ull acc[4][4];
                    #pragma unroll
                    for (int G = 0; G < 4; G++) {
                        acc[G][0] = bias2[G]; acc[G][1] = bias2[G];
                        acc[G][2] = bias2[G]; acc[G][3] = bias2[G];
                    }
                    #pragma unroll
                    for (int kk = 0; kk < 13; kk++) {
                        ulonglong2 S0 = sp[2 * kk], S1 = sp[2 * kk + 1];
                        #pragma unroll
                        for (int G = 0; G < 4; G++) {
                            ull w2 = splat2(wi[G][kk]);
                            acc[G][0] = ffma2(S0.x, w2, acc[G][0]);
                            acc[G][1] = ffma2(S0.y, w2, acc[G][1]);
                            acc[G][2] = ffma2(S1.x, w2, acc[G][2]);
                            acc[G][3] = ffma2(S1.y, w2, acc[G][3]);
                        }
                    }
                    #pragma unroll
                    for (int G = 0; G < 4; G++) {
                        ulonglong2 s0; s0.x = acc[G][0]; s0.y = acc[G][1];
                        ulonglong2 s1; s1.x = acc[G][2]; s1.y = acc[G][3];
                        *(ulonglong2*)&gq[(G * 51 + j) * BT]     = s0;
                        *(ulonglong2*)&gq[(G * 51 + j) * BT + 4] = s1;
                    }
                } else if (kq == 0) {   // role 0 rank-1 input term
                    const ulonglong2* xp =
                        (const ulonglong2*)(xchk + ((s >> 5) & 1) * 256 + (s & 31) * 8);
                    ulonglong2 X0 = xp[0], X1 = xp[1];
                    #pragma unroll
                    for (int G = 0; G < 4; G++) {
                        ull a0 = ffma2(X0.x, w1_2[G], bias2[G]);
                        ull a1 = ffma2(X0.y, w1_2[G], bias2[G]);
                        ull a2 = ffma2(X1.x, w1_2[G], bias2[G]);
                        ull a3 = ffma2(X1.y, w1_2[G], bias2[G]);
                        ulonglong2 s0; s0.x = a0; s0.y = a1;
                        ulonglong2 s1; s1.x = a2; s1.y = a3;
                        *(ulonglong2*)&gq[(G * 51 + j) * BT]     = s0;
                        *(ulonglong2*)&gq[(G * 51 + j) * BT + 4] = s1;
                    }
                }
            }
            BAR_SYNC(B_II, CNT_I);            // quadrants(s) written

            // ---- pre-sum 4 quadrants -> ginsum[s&3] (2 float4 per lane) ----
            if (itid < 204) {
                const float4* q = (const float4*)(ginq + (s & 1) * 4 * GSZ);
                float4* dsum = (float4*)(ginsum + (s & 3) * GSZ);
                #pragma unroll
                for (int r = 0; r < 2; r++) {
                    const int i = itid + r * 204;
                    float4 v0 = q[i], v1 = q[408 + i], v2 = q[816 + i], v3 = q[1224 + i];
                    float4 o;
                    o.x = (v0.x + v1.x) + (v2.x + v3.x);
                    o.y = (v0.y + v1.y) + (v2.y + v3.y);
                    o.z = (v0.z + v1.z) + (v2.z + v3.z);
                    o.w = (v0.w + v1.w) + (v2.w + v3.w);
                    dsum[i] = o;
                }
            }
            MEMBAR_CTA();
            BAR_ARRIVE(B_IN0 + (s & 3), CNT_RI);   // ginsum(s) ready
        }
    } else {
        // ============================ comm warp ============================
        const int lane = tid - C0;
        for (int k = 0; k < TN; k++) {
            BAR_SYNC(B_XC, CNT_XC);
            if (role > 0 && k + DPRE < TN) {
                if (lane == 0) wait_ge(&g_prod[role - 1][g], (unsigned)(k + DPRE + 1));
                __syncwarp();
                const float4* s4 =
                    (const float4*)(ring_in + ((k + DPRE) & (NSLOT - 1)) * EBT);
                float4* d4 = (float4*)(xin + ((k + DPRE) & (XBUF - 1)) * 416);
                for (int i = lane; i < EBT / 4; i += 32) d4[i] = ldcg4(s4 + i);
                __syncwarp();
                if (lane == 0) st_rel(&g_cons[role - 1][g], (unsigned)(k + DPRE + 1));
            }
            if (role == 0 && (k & 31) == 0 && k + 32 < TN) {
                const int w = ((k >> 5) + 1) & 1;
                #pragma unroll
                for (int b = 0; b < BT; b++)
                    xchk[w * 256 + lane * 8 + b] =
                        x[(size_t)(g * BT + b) * TN + (k + 32 + lane)];
            }
        }
    }
}

extern "C" void kernel_launch(void* const* d_in, const int* in_sizes, int n_in,
                              void* d_out, int out_size)
{
    (void)in_sizes; (void)n_in; (void)out_size;
    const float* x    = (const float*)d_in[0];
    const float* Wih1 = (const float*)d_in[1];
    const float* Whh1 = (const float*)d_in[2];
    const float* bih1 = (const float*)d_in[3];
    const float* bhh1 = (const float*)d_in[4];
    const float* Wih  = (const float*)d_in[5];
    const float* Whh  = (const float*)d_in[6];
    const float* bih  = (const float*)d_in[7];
    const float* bhh  = (const float*)d_in[8];
    const float* Wl   = (const float*)d_in[9];
    const float* bl   = (const float*)d_in[10];
    float* out = (float*)d_out;

    const int smem_bytes = 27156 * 4;  // 108624
    cudaFuncSetAttribute(lstm_kernel, cudaFuncAttributeMaxDynamicSharedMemorySize,
                         smem_bytes);

    reset_kernel<<<1, 64>>>();
    lstm_kernel<<<3 * NG, NTH, smem_bytes>>>(x, Wih1, Whh1, bih1, bhh1,
                                             Wih, Whh, bih, bhh, Wl, bl, out);
}

// round 15
// speedup vs baseline: 1.3878x; 1.1706x over previous
#include <cuda_runtime.h>

// ---------------------------------------------------------------------------
// 5-layer stacked LSTM, H=51, B=256, T=2048. Output depends only on layer-3 h
// => layers 4,5 dead. 3 roles (L1,L2,L3) x 32 batch groups = 96 CTAs.
// R12 decoupled-domain structure (measured optimum: 15 warps):
//   R group (warps 0-6):  recurrent GEMV(t) -> cell(t)   [serial chain]
//   I group (warps 7-13): input GEMV(s), 2 rows x half-k per lane
//   comm warp (14):       ring prefetch D=4, paced with I
// vs R12: gin has 2 partials (not 4) -> cell loads 24->16 per element, with
// no extra barriers/passes; I->R handoff 4-deep (parity t&3) absorbs jitter.
// tanh.approx activations (sigmoid x/2 folded into weights), c in registers.
// ---------------------------------------------------------------------------

#define HN 51
#define NJ 204
#define TN 2048
#define NG 32
#define BT 8
#define NSLOT 16
#define XBUF 8
#define DPRE 4
#define NTH 480
#define I0   224              // first tid of I group
#define C0   448              // first tid of comm warp
#define EBT  408              // HN*BT
#define GSZ  1632             // NJ*BT

// named barrier ids / counts
#define B_IN0 2               // ids 2..5  : gin(s) ready     (I arrive, R sync)
#define B_FR0 6               // ids 6..9  : gin slot free    (R arrive, I sync)
#define B_RH  10              // R-internal: h(t) complete
#define B_XC  11              // I+comm pacing
#define CNT_RI 448
#define CNT_R  224
#define CNT_XC 256

typedef unsigned long long ull;

__device__ float    g_hbuf[2][NG][NSLOT][EBT];
__device__ unsigned g_prod[2][NG];
__device__ unsigned g_cons[2][NG];

__device__ __forceinline__ unsigned ld_acq(const unsigned* p) {
    unsigned v;
    asm volatile("ld.global.acquire.gpu.u32 %0, [%1];" : "=r"(v) : "l"(p));
    return v;
}
__device__ __forceinline__ void st_rel(unsigned* p, unsigned v) {
    asm volatile("st.global.release.gpu.u32 [%0], %1;" :: "l"(p), "r"(v));
}
__device__ __forceinline__ void wait_ge(unsigned* p, unsigned v) {
    if (ld_acq(p) >= v) return;
    while (ld_acq(p) < v) __nanosleep(32);
}
__device__ __forceinline__ float4 ldcg4(const float4* p) {
    float4 v;
    asm volatile("ld.global.cg.v4.f32 {%0,%1,%2,%3}, [%4];"
                 : "=f"(v.x), "=f"(v.y), "=f"(v.z), "=f"(v.w) : "l"(p));
    return v;
}
__device__ __forceinline__ ull ffma2(ull a, ull b, ull c) {
    ull d;
    asm("fma.rn.f32x2 %0, %1, %2, %3;" : "=l"(d) : "l"(a), "l"(b), "l"(c));
    return d;
}
__device__ __forceinline__ ull splat2(float x) {
    ull d; unsigned u = __float_as_uint(x);
    asm("mov.b64 %0, {%1, %2};" : "=l"(d) : "r"(u), "r"(u));
    return d;
}
__device__ __forceinline__ float tanha(float x) {
    float y;
    asm("tanh.approx.f32 %0, %1;" : "=f"(y) : "f"(x));
    return y;
}
__device__ __forceinline__ float sig_h(float y) {   // arg pre-halved
    return fmaf(0.5f, tanha(y), 0.5f);
}
#define BAR_SYNC(id, cnt)   asm volatile("bar.sync %0, %1;"   :: "r"(id), "r"(cnt) : "memory")
#define BAR_ARRIVE(id, cnt) asm volatile("bar.arrive %0, %1;" :: "r"(id), "r"(cnt) : "memory")
#define MEMBAR_CTA()        asm volatile("membar.cta;" ::: "memory")

__global__ void __launch_bounds__(64, 1) reset_kernel() {
    int i = threadIdx.x;
    if (i < NG) {
        g_prod[0][i] = 0; g_prod[1][i] = 0;
        g_cons[0][i] = 0; g_cons[1][i] = 0;
    }
}

__global__ void __launch_bounds__(NTH, 1) lstm_kernel(
    const float* __restrict__ x,    const float* __restrict__ Wih1,
    const float* __restrict__ Whh1, const float* __restrict__ bih1,
    const float* __restrict__ bhh1, const float* __restrict__ Wih,
    const float* __restrict__ Whh,  const float* __restrict__ bih,
    const float* __restrict__ bhh,  const float* __restrict__ Wl,
    const float* __restrict__ bl,   float* __restrict__ out)
{
    extern __shared__ float sm[];
    float* grec = sm;                 // [2 kh][GSZ]            3264
    float* gin  = sm + 3264;          // [4 par][2 kh][GSZ]     13056
    float* xin  = sm + 16320;         // [XBUF][52*8]           3328 (row 51 zero)
    float* h_t  = sm + 19648;         // [52*8] (row 51 zero)   416
    float* xchk = sm + 20064;         // [2][32][8]             512
    float* wl_s = sm + 20576;         // [52]
    // total 20628 floats = 82512 bytes

    const int tid  = threadIdx.x;
    const int role = blockIdx.x / NG;   // 0=L1, 1=L2, 2=L3
    const int g    = blockIdx.x % NG;

    // ---------------- group-specific weight loads ----------------
    // Both R and I lanes: 2 gate rows x half-k (26 iters, k=25 overlap zeroed
    // in the kh=1 half). i,f,o rows pre-scaled by 0.5 for tanh-only sigmoid.
    float w0[26], w1[26];
    ull biasA = 0, biasB = 0, w1A = 0, w1B = 0;
    int kb = 0, r0 = 0;

    if (tid < 204) {                      // R GEMV lane (recurrent weights)
        const int kh = tid / 102, jp = tid % 102;
        r0 = 2 * jp; kb = kh * 25;
        const float* W = (role == 0) ? Whh1 : (Whh + (role - 1) * NJ * HN);
        const float sc0 = ((r0     / 51) == 2) ? 1.f : 0.5f;
        const float sc1 = (((r0+1) / 51) == 2) ? 1.f : 0.5f;
        #pragma unroll
        for (int kk = 0; kk < 26; kk++) {
            int k = kb + kk;
            bool z = (kh == 1 && kk == 0);
            w0[kk] = z ? 0.f : sc0 * W[ r0      * HN + k];
            w1[kk] = z ? 0.f : sc1 * W[(r0 + 1) * HN + k];
        }
    } else if (tid >= I0 && tid < I0 + 204) {   // I GEMV lane (input weights)
        const int itid = tid - I0;
        const int kh = itid / 102, jp = itid % 102;
        r0 = 2 * jp; kb = kh * 25;
        const float sc0 = ((r0     / 51) == 2) ? 1.f : 0.5f;
        const float sc1 = (((r0+1) / 51) == 2) ? 1.f : 0.5f;
        if (role > 0) {
            const int l = role - 1;
            const float* W = Wih + l * NJ * HN;
            #pragma unroll
            for (int kk = 0; kk < 26; kk++) {
                int k = kb + kk;
                bool z = (kh == 1 && kk == 0);
                w0[kk] = z ? 0.f : sc0 * W[ r0      * HN + k];
                w1[kk] = z ? 0.f : sc1 * W[(r0 + 1) * HN + k];
            }
            if (kh == 0) {
                biasA = splat2(sc0 * (bih[l * NJ + r0]     + bhh[l * NJ + r0]));
                biasB = splat2(sc1 * (bih[l * NJ + r0 + 1] + bhh[l * NJ + r0 + 1]));
            }
        } else if (kh == 0) {   // role 0: rank-1 input term
            w1A   = splat2(sc0 * Wih1[r0]);
            w1B   = splat2(sc1 * Wih1[r0 + 1]);
            biasA = splat2(sc0 * (bih1[r0]     + bhh1[r0]));
            biasB = splat2(sc1 * (bih1[r0 + 1] + bhh1[r0 + 1]));
        }
    }
    const float blv = (role == 2) ? bl[0] : 0.f;

    for (int i = tid; i < 20628; i += NTH) sm[i] = 0.f;
    __syncthreads();
    if (role == 2 && tid < HN) wl_s[tid] = Wl[tid];
    __syncthreads();

    float*       ring_out = (role < 2) ? &g_hbuf[role][g][0][0]     : (float*)0;
    const float* ring_in  = (role > 0) ? &g_hbuf[role - 1][g][0][0] : (const float*)0;

    // ---- prologue: comm warp fills xin slots 0..3 / x window 0 ----
    if (tid >= C0) {
        const int lane = tid - C0;
        if (role > 0) {
            for (int d = 0; d < DPRE; d++) {
                if (lane == 0) wait_ge(&g_prod[role - 1][g], (unsigned)(d + 1));
                __syncwarp();
                const float4* s4 = (const float4*)(ring_in + d * EBT);
                float4* d4 = (float4*)(xin + d * 416);
                for (int i = lane; i < EBT / 4; i += 32) d4[i] = ldcg4(s4 + i);
                __syncwarp();
                if (lane == 0) st_rel(&g_cons[role - 1][g], (unsigned)(d + 1));
            }
        } else {
            #pragma unroll
            for (int b = 0; b < BT; b++)
                xchk[lane * 8 + b] = x[(size_t)(g * BT + b) * TN + lane];
        }
    }
    __syncthreads();

    // =====================================================================
    if (tid < I0) {
        // ============================ R group ============================
        float c_a = 0.f, c_b = 0.f;
        const int  kh = (tid < 204) ? tid / 102 : 0;
        const bool lane_out = (role == 2) && (tid >= 204 && tid < 212);
        const bool lane_bp  = (role <  2) && (tid == 212);

        for (int t = 0; t < TN; t++) {
            // ---- recurrent GEMV(t) over h(t-1) ----
            if (tid < 204) {
                const ulonglong2* hp = (const ulonglong2*)(h_t + kb * BT);
                ull a00 = 0, a01 = 0, a02 = 0, a03 = 0;
                ull a10 = 0, a11 = 0, a12 = 0, a13 = 0;
                #pragma unroll
                for (int kk = 0; kk < 26; kk++) {
                    ulonglong2 S0 = hp[2 * kk], S1 = hp[2 * kk + 1];
                    ull q0 = splat2(w0[kk]);
                    ull q1 = splat2(w1[kk]);
                    a00 = ffma2(S0.x, q0, a00); a01 = ffma2(S0.y, q0, a01);
                    a02 = ffma2(S1.x, q0, a02); a03 = ffma2(S1.y, q0, a03);
                    a10 = ffma2(S0.x, q1, a10); a11 = ffma2(S0.y, q1, a11);
                    a12 = ffma2(S1.x, q1, a12); a13 = ffma2(S1.y, q1, a13);
                }
                float* gr = grec + kh * GSZ + r0 * BT;
                ulonglong2 s;
                s.x = a00; s.y = a01; *(ulonglong2*)(gr)          = s;
                s.x = a02; s.y = a03; *(ulonglong2*)(gr + 4)      = s;
                s.x = a10; s.y = a11; *(ulonglong2*)(gr + BT)     = s;
                s.x = a12; s.y = a13; *(ulonglong2*)(gr + BT + 4) = s;
            } else {
                if (lane_out && t > 0) {                 // out(t-1) from h(t-1)
                    const int b = tid - 204;
                    float a = blv;
                    #pragma unroll
                    for (int u = 0; u < HN; u++) a += h_t[u * BT + b] * wl_s[u];
                    out[(size_t)(g * BT + b) * TN + (t - 1)] = a;
                }
                if (lane_bp && t >= NSLOT)
                    wait_ge(&g_cons[role][g], (unsigned)(t - (NSLOT - 1)));
            }

            BAR_SYNC(B_IN0 + (t & 3), CNT_RI);   // gin(t) ready; grec drained

            // ---- cell(t): elements tid and tid+224 (16 LDS/elem) ----
            {
                const float* gi = gin + (t & 3) * 2 * GSZ;
                float* rslot = (role < 2) ? (ring_out + (t & (NSLOT - 1)) * EBT)
                                          : (float*)0;
                {
                    const int e = tid;
                    float yi = (grec[e]        + grec[GSZ + e])
                             + (gi[e]          + gi[GSZ + e]);
                    float yf = (grec[408 + e]  + grec[GSZ + 408 + e])
                             + (gi[408 + e]    + gi[GSZ + 408 + e]);
                    float gg = (grec[816 + e]  + grec[GSZ + 816 + e])
                             + (gi[816 + e]    + gi[GSZ + 816 + e]);
                    float yo = (grec[1224 + e] + grec[GSZ + 1224 + e])
                             + (gi[1224 + e]   + gi[GSZ + 1224 + e]);
                    float c = sig_h(yf) * c_a + sig_h(yi) * tanha(gg);
                    float h = sig_h(yo) * tanha(c);
                    c_a = c; h_t[e] = h;
                    if (role < 2) rslot[e] = h;
                }
                if (tid < 184) {
                    const int e = tid + 224;
                    float yi = (grec[e]        + grec[GSZ + e])
                             + (gi[e]          + gi[GSZ + e]);
                    float yf = (grec[408 + e]  + grec[GSZ + 408 + e])
                             + (gi[408 + e]    + gi[GSZ + 408 + e]);
                    float gg = (grec[816 + e]  + grec[GSZ + 816 + e])
                             + (gi[816 + e]    + gi[GSZ + 816 + e]);
                    float yo = (grec[1224 + e] + grec[GSZ + 1224 + e])
                             + (gi[1224 + e]   + gi[GSZ + 1224 + e]);
                    float c = sig_h(yf) * c_b + sig_h(yi) * tanha(gg);
                    float h = sig_h(yo) * tanha(c);
                    c_b = c; h_t[e] = h;
                    if (role < 2) rslot[e] = h;
                }
            }

            BAR_ARRIVE(B_FR0 + (t & 3), CNT_RI); // gin slot (t&3) consumed
            BAR_SYNC(B_RH, CNT_R);               // h(t) + ring STGs complete
            if (role < 2 && tid == 0) st_rel(&g_prod[role][g], (unsigned)(t + 1));
        }
        // epilogue: out(TN-1)
        if (lane_out) {
            const int b = tid - 204;
            float a = blv;
            #pragma unroll
            for (int u = 0; u < HN; u++) a += h_t[u * BT + b] * wl_s[u];
            out[(size_t)(g * BT + b) * TN + (TN - 1)] = a;
        }
    } else if (tid < C0) {
        // ============================ I group ============================
        const int itid = tid - I0;
        const int kh = (itid < 204) ? itid / 102 : 0;

        for (int s = 0; s < TN; s++) {
            BAR_SYNC(B_XC, CNT_XC);                        // xin(s)/xchk ready
            if (s >= 4) BAR_SYNC(B_FR0 + (s & 3), CNT_RI); // gin[s&3] free

            if (itid < 204) {
                float* gq = gin + (s & 3) * 2 * GSZ + kh * GSZ;
                if (role > 0) {
                    const ulonglong2* sp =
                        (const ulonglong2*)(xin + (s & (XBUF - 1)) * 416 + kb * BT);
                    ull a00 = biasA, a01 = biasA, a02 = biasA, a03 = biasA;
                    ull a10 = biasB, a11 = biasB, a12 = biasB, a13 = biasB;
                    #pragma unroll
                    for (int kk = 0; kk < 26; kk++) {
                        ulonglong2 S0 = sp[2 * kk], S1 = sp[2 * kk + 1];
                        ull q0 = splat2(w0[kk]);
                        ull q1 = splat2(w1[kk]);
                        a00 = ffma2(S0.x, q0, a00); a01 = ffma2(S0.y, q0, a01);
                        a02 = ffma2(S1.x, q0, a02); a03 = ffma2(S1.y, q0, a03);
                        a10 = ffma2(S0.x, q1, a10); a11 = ffma2(S0.y, q1, a11);
                        a12 = ffma2(S1.x, q1, a12); a13 = ffma2(S1.y, q1, a13);
                    }
                    ulonglong2 v;
                    float* gw = gq + r0 * BT;
                    v.x = a00; v.y = a01; *(ulonglong2*)(gw)          = v;
                    v.x = a02; v.y = a03; *(ulonglong2*)(gw + 4)      = v;
                    v.x = a10; v.y = a11; *(ulonglong2*)(gw + BT)     = v;
                    v.x = a12; v.y = a13; *(ulonglong2*)(gw + BT + 4) = v;
                } else if (kh == 0) {   // role 0 rank-1 input term
                    const ulonglong2* xp =
                        (const ulonglong2*)(xchk + ((s >> 5) & 1) * 256 + (s & 31) * 8);
                    ulonglong2 X0 = xp[0], X1 = xp[1];
                    ull a0 = ffma2(X0.x, w1A, biasA);
                    ull a1 = ffma2(X0.y, w1A, biasA);
                    ull a2 = ffma2(X1.x, w1A, biasA);
                    ull a3 = ffma2(X1.y, w1A, biasA);
                    ull b0 = ffma2(X0.x, w1B, biasB);
                    ull b1 = ffma2(X0.y, w1B, biasB);
                    ull b2 = ffma2(X1.x, w1B, biasB);
                    ull b3 = ffma2(X1.y, w1B, biasB);
                    ulonglong2 v;
                    float* gw = gq + r0 * BT;
                    v.x = a0; v.y = a1; *(ulonglong2*)(gw)          = v;
                    v.x = a2; v.y = a3; *(ulonglong2*)(gw + 4)      = v;
                    v.x = b0; v.y = b1; *(ulonglong2*)(gw + BT)     = v;
                    v.x = b2; v.y = b3; *(ulonglong2*)(gw + BT + 4) = v;
                }
            }
            MEMBAR_CTA();
            BAR_ARRIVE(B_IN0 + (s & 3), CNT_RI);   // gin(s) ready
        }
    } else {
        // ============================ comm warp ============================
        const int lane = tid - C0;
        for (int k = 0; k < TN; k++) {
            BAR_SYNC(B_XC, CNT_XC);
            if (role > 0 && k + DPRE < TN) {
                if (lane == 0) wait_ge(&g_prod[role - 1][g], (unsigned)(k + DPRE + 1));
                __syncwarp();
                const float4* s4 =
                    (const float4*)(ring_in + ((k + DPRE) & (NSLOT - 1)) * EBT);
                float4* d4 = (float4*)(xin + ((k + DPRE) & (XBUF - 1)) * 416);
                for (int i = lane; i < EBT / 4; i += 32) d4[i] = ldcg4(s4 + i);
                __syncwarp();
                if (lane == 0) st_rel(&g_cons[role - 1][g], (unsigned)(k + DPRE + 1));
            }
            if (role == 0 && (k & 31) == 0 && k + 32 < TN) {
                const int w = ((k >> 5) + 1) & 1;
                #pragma unroll
                for (int b = 0; b < BT; b++)
                    xchk[w * 256 + lane * 8 + b] =
                        x[(size_t)(g * BT + b) * TN + (k + 32 + lane)];
            }
        }
    }
}

extern "C" void kernel_launch(void* const* d_in, const int* in_sizes, int n_in,
                              void* d_out, int out_size)
{
    (void)in_sizes; (void)n_in; (void)out_size;
    const float* x    = (const float*)d_in[0];
    const float* Wih1 = (const float*)d_in[1];
    const float* Whh1 = (const float*)d_in[2];
    const float* bih1 = (const float*)d_in[3];
    const float* bhh1 = (const float*)d_in[4];
    const float* Wih  = (const float*)d_in[5];
    const float* Whh  = (const float*)d_in[6];
    const float* bih  = (const float*)d_in[7];
    const float* bhh  = (const float*)d_in[8];
    const float* Wl   = (const float*)d_in[9];
    const float* bl   = (const float*)d_in[10];
    float* out = (float*)d_out;

    const int smem_bytes = 20628 * 4;  // 82512
    cudaFuncSetAttribute(lstm_kernel, cudaFuncAttributeMaxDynamicSharedMemorySize,
                         smem_bytes);

    reset_kernel<<<1, 64>>>();
    lstm_kernel<<<3 * NG, NTH, smem_bytes>>>(x, Wih1, Whh1, bih1, bhh1,
                                             Wih, Whh, bih, bhh, Wl, bl, out);
}